// round 14
// baseline (speedup 1.0000x reference)
#include <cuda_runtime.h>
#include <cstdint>

#define Hh 2048
#define Ww 2048
#define NPIX (Hh*Ww)            // 4194304
#define BIGL NPIX               // background label
#define NLBL (NPIX+1)
#define KTOP 16
#define NBLK_TOP 120
#define MINSZ 64

// ---------------- device scratch (no allocations allowed) ----------------
__device__ int   g_labA[NPIX];
__device__ int   g_labB[NPIX];
__device__ int   g_counts[NLBL];
__device__ unsigned long long g_cand[NBLK_TOP*KTOP];
__device__ int   g_lids[KTOP];
__device__ int   g_cnts[KTOP];
__device__ int   g_bbox[KTOP][4];
__device__ int   g_cls[KTOP];
__device__ float g_roi[KTOP*227*227];
__device__ float g_h1[KTOP*16*56*56];
__device__ float g_h2[KTOP*32*27*27];
__device__ float g_U[16*32*32];                // Winograd-transformed w2: [j][ic][oc]

// ---------------- helpers ----------------
__device__ __forceinline__ unsigned long long pack2(float v){
    unsigned long long r; asm("mov.b64 %0, {%1, %1};" : "=l"(r) : "f"(v)); return r;
}
__device__ __forceinline__ void fma2(unsigned long long& a, unsigned long long v, unsigned long long w){
    asm("fma.rn.f32x2 %0, %1, %2, %0;" : "+l"(a) : "l"(v), "l"(w));
}
__device__ __forceinline__ float2 unpack2(unsigned long long a){
    float2 f; asm("mov.b64 {%0, %1}, %2;" : "=f"(f.x), "=f"(f.y) : "l"(a)); return f;
}

// ================= weight transform: U = G w2 G^T per (ic,oc) =================
__global__ void k_uw(const float* __restrict__ w2){
    int t = threadIdx.x;            // 1024 = 32 ic x 32 oc
    int ic = t >> 5, oc = t & 31;
    const float* gp = w2 + ((size_t)oc*32 + ic)*9;
    float g0[3], g1[3], g2[3];
    #pragma unroll
    for (int c = 0; c < 3; c++){ g0[c] = gp[c]; g1[c] = gp[3+c]; g2[c] = gp[6+c]; }
    float T[4][3];
    #pragma unroll
    for (int c = 0; c < 3; c++){
        T[0][c] = g0[c];
        T[1][c] = 0.5f*(g0[c] + g1[c] + g2[c]);
        T[2][c] = 0.5f*(g0[c] - g1[c] + g2[c]);
        T[3][c] = g2[c];
    }
    #pragma unroll
    for (int r = 0; r < 4; r++){
        float u0 = T[r][0];
        float u1 = 0.5f*(T[r][0] + T[r][1] + T[r][2]);
        float u2 = 0.5f*(T[r][0] - T[r][1] + T[r][2]);
        float u3 = T[r][2];
        g_U[(r*4+0)*1024 + ic*32 + oc] = u0;
        g_U[(r*4+1)*1024 + ic*32 + oc] = u1;
        g_U[(r*4+2)*1024 + ic*32 + oc] = u2;
        g_U[(r*4+3)*1024 + ic*32 + oc] = u3;
    }
}

// ================= Winograd F(2x2,3x3) fused conv — 2 oc-passes, 2 blocks/SM =================
// 16x16 px block, 256 threads: thread = (tile 0..63, ocg 0..3); per pass thread owns 4 oc.
// Math identical to R13 (rel_err 0.0); restructured: full sV per g (1 barrier), M[32] accs.
#define W_SF 0          // feat group [8ch][18*18=324] = 2592
#define W_SV 2592       // V: [8icl][16 j][64 tiles] = 8192
#define W_SU 10784      // [8icl][16 j][16 oc] = 2048
#define W_SX 12832      // [20][21] = 420
#define W_W1 13252      // [9tap][32oc] = 288
#define W_W3 13540      // 32
#define W_SZ 13572      // [64 tiles][4 sub][4 ocg] = 1024
#define W_TOTAL ((13572+1024)*4)   // 58384 B

__global__ void __launch_bounds__(256, 2) k_conv_wino(const float* __restrict__ x,
                                                      const float* __restrict__ w1,
                                                      const float* __restrict__ w3){
    extern __shared__ float sm[];
    float* sF  = sm + W_SF;
    float* sV  = sm + W_SV;
    float* sU  = sm + W_SU;
    float* sX  = sm + W_SX;
    float* sW1 = sm + W_W1;
    float* sW3 = sm + W_W3;
    float* sZ  = sm + W_SZ;

    int tid = threadIdx.x;
    int tile = tid >> 2, ocg = tid & 3;          // ocg doubles as transform row p
    int ty = tile >> 3, tx = tile & 7;

    for (int i = tid; i < 288; i += 256){
        int tap = i >> 5, oc = i & 31;
        sW1[i] = w1[oc*9 + tap];                 // [tap][oc]
    }
    if (tid < 32) sW3[tid] = w3[tid];

    int by0 = blockIdx.y*16, bx0 = blockIdx.x*16;
    // input 20x20 (stride 21), origin (by0-2, bx0-2), zero-padded
    for (int i = tid; i < 400; i += 256){
        int r = i/20, c = i - r*20;
        int gy = by0 - 2 + r, gx = bx0 - 2 + c;
        float v = 0.f;
        if ((unsigned)gy < 2048u && (unsigned)gx < 2048u) v = x[(gy<<11)+gx];
        sX[r*21 + c] = v;
    }

    // per-thread constants for the B-transform row p = ocg
    int p = ocg;
    int ra = (p==0) ? 0 : (p==2) ? 2 : 1;        // {0,1,2,1}
    int rb = (p==3) ? 3 : (p==2) ? 1 : 2;        // {2,2,1,3}
    bool plus = (p == 1);
    int fb_off = (2*ty)*18 + 2*tx;               // d window origin in sF channel
    const unsigned long long* w1u = (const unsigned long long*)sW1;

    float z0 = 0.f, z1 = 0.f, z2 = 0.f, z3 = 0.f;

    for (int pass = 0; pass < 2; pass++){
        unsigned long long M[32];
        #pragma unroll
        for (int i = 0; i < 32; i++) M[i] = 0ull;

        for (int g = 0; g < 4; g++){
            __syncthreads();   // prior (pass,g) sV/sU readers done; first iter orders sX writes
            // stage U for this (pass, ic group): [icl][j][16 oc]
            for (int i = tid; i < 2048; i += 256){
                int icl = i >> 8, rem = i & 255, j = rem >> 4, oc = rem & 15;
                sU[i] = g_U[j*1024 + (g*8+icl)*32 + pass*16 + oc];
            }
            // conv1 (exact fp32, identical to all passing rounds) for ch g*8..g*8+7 over 18x18
            for (int i = tid; i < 324; i += 256){
                int fy = i/18, fx = i - fy*18;
                const float* base = sX + fy*21 + fx;
                unsigned long long vp[9];
                #pragma unroll
                for (int r = 0; r < 3; r++)
                    #pragma unroll
                    for (int c = 0; c < 3; c++) vp[r*3+c] = pack2(base[r*21+c]);
                #pragma unroll
                for (int q = 0; q < 4; q++){
                    unsigned long long a = 0ull;
                    #pragma unroll
                    for (int t = 0; t < 9; t++) fma2(a, vp[t], w1u[t*16 + g*4 + q]);
                    float2 f = unpack2(a);
                    sF[(2*q  )*324 + i] = fmaxf(f.x, 0.f);
                    sF[(2*q+1)*324 + i] = fmaxf(f.y, 0.f);
                }
            }
            __syncthreads();

            // V transform for ALL 8 ic of this group (row p per thread), identical math to R13
            #pragma unroll
            for (int icl = 0; icl < 8; icl++){
                const float* fb = sF + icl*324 + fb_off;
                const float* fa = fb + ra*18;
                const float* fbb = fb + rb*18;
                float c0, c1, c2, c3;
                if (plus){ c0 = fa[0]+fbb[0]; c1 = fa[1]+fbb[1]; c2 = fa[2]+fbb[2]; c3 = fa[3]+fbb[3]; }
                else     { c0 = fa[0]-fbb[0]; c1 = fa[1]-fbb[1]; c2 = fa[2]-fbb[2]; c3 = fa[3]-fbb[3]; }
                float* vb = sV + icl*1024;
                vb[(p*4+0)*64 + tile] = c0 - c2;
                vb[(p*4+1)*64 + tile] = c1 + c2;
                vb[(p*4+2)*64 + tile] = c2 - c1;
                vb[(p*4+3)*64 + tile] = c1 - c3;
            }
            __syncthreads();

            // accumulate: M[j] += V[icl][j][tile] * U[icl][j][4 oc of this thread]
            #pragma unroll
            for (int icl = 0; icl < 8; icl++){
                const float* vbuf = sV + icl*1024;
                const unsigned long long* ub = (const unsigned long long*)(sU + icl*256) + ocg*2;
                #pragma unroll
                for (int j = 0; j < 16; j++){
                    unsigned long long vb = pack2(vbuf[j*64 + tile]);
                    const unsigned long long* up = ub + j*8;
                    fma2(M[j*2+0], vb, up[0]);
                    fma2(M[j*2+1], vb, up[1]);
                }
            }
        }

        // per-pass epilogue: output transform A^T M A per oc (4 oc), relu, w3-weighted z
        #pragma unroll
        for (int o = 0; o < 4; o++){
            int q = o >> 1, h = o & 1;
            float m[16];
            #pragma unroll
            for (int j = 0; j < 16; j++){
                float2 f = unpack2(M[j*2+q]);
                m[j] = h ? f.y : f.x;
            }
            float s00 = m[0] + m[4] + m[8];
            float s01 = m[1] + m[5] + m[9];
            float s02 = m[2] + m[6] + m[10];
            float s03 = m[3] + m[7] + m[11];
            float s10 = m[4] - m[8] - m[12];
            float s11 = m[5] - m[9] - m[13];
            float s12 = m[6] - m[10] - m[14];
            float s13 = m[7] - m[11] - m[15];
            float o00 = s00 + s01 + s02;
            float o01 = s01 - s02 - s03;
            float o10 = s10 + s11 + s12;
            float o11 = s11 - s12 - s13;
            float wc = sW3[pass*16 + ocg*4 + o];
            z0 += fmaxf(o00, 0.f)*wc;
            z1 += fmaxf(o01, 0.f)*wc;
            z2 += fmaxf(o10, 0.f)*wc;
            z3 += fmaxf(o11, 0.f)*wc;
        }
    }

    sZ[tile*16 + 0*4 + ocg] = z0;
    sZ[tile*16 + 1*4 + ocg] = z1;
    sZ[tile*16 + 2*4 + ocg] = z2;
    sZ[tile*16 + 3*4 + ocg] = z3;
    __syncthreads();

    // final: one thread per pixel, deterministic oc-group order sum, threshold
    {
        int y = tid >> 4, xl = tid & 15;
        int tl = (y >> 1)*8 + (xl >> 1);
        int sub = (y & 1)*2 + (xl & 1);
        const float* zp = sZ + tl*16 + sub*4;
        float z = ((zp[0] + zp[1]) + zp[2]) + zp[3];
        int pp = ((by0 + y) << 11) + bx0 + xl;
        g_labA[pp] = (z > 0.f) ? pp : BIGL;
    }
}

// ================= connected components (R7: early-exit, int4, sentinel ring) =================
#define CC_STRIDE 88
#define CC_CELLS  (82*CC_STRIDE)
#define CC_SMEM   (2*CC_CELLS*4)

__device__ __forceinline__ int cc_step(const int* __restrict__ cur, int* __restrict__ nxt, int off){
    int4 c = *(const int4*)(cur + off);
    int4 u = *(const int4*)(cur + off - CC_STRIDE);
    int4 d = *(const int4*)(cur + off + CC_STRIDE);
    int l = cur[off-1], r = cur[off+4];
    int4 o; int m;
    m = min(min(u.x,d.x), min(l,   c.y)); o.x = (c.x==BIGL) ? BIGL : min(c.x, m);
    m = min(min(u.y,d.y), min(c.x, c.z)); o.y = (c.y==BIGL) ? BIGL : min(c.y, m);
    m = min(min(u.z,d.z), min(c.y, c.w)); o.z = (c.z==BIGL) ? BIGL : min(c.z, m);
    m = min(min(u.w,d.w), min(c.z, r  )); o.w = (c.w==BIGL) ? BIGL : min(c.w, m);
    *(int4*)(nxt + off) = o;
    return (o.x^c.x) | (o.y^c.y) | (o.z^c.z) | (o.w^c.w);
}

__global__ __launch_bounds__(1024) void k_cc(const int* __restrict__ src, int* __restrict__ dst){
    extern __shared__ int sh[];
    int* A = sh;
    int* B = sh + CC_CELLS;
    int tid = threadIdx.x;
    int gx0 = blockIdx.x*64 - 8, gy0 = blockIdx.y*64 - 8;
    for (int s = tid; s < CC_CELLS; s += 1024){ A[s] = BIGL; B[s] = BIGL; }
    __syncthreads();
    for (int v = tid; v < 1600; v += 1024){
        int vy = v/20, vx = (v%20)*4;
        int gy = gy0 + vy, gxb = gx0 + vx;
        int off = (1+vy)*CC_STRIDE + 4 + vx;
        if ((unsigned)gy < 2048u && gxb >= 0 && gxb + 3 < 2048){
            *(int4*)(A + off) = *(const int4*)(src + (gy<<11) + gxb);
        } else if ((unsigned)gy < 2048u){
            #pragma unroll
            for (int k = 0; k < 4; k++){
                int gx = gxb + k;
                A[off+k] = ((unsigned)gx < 2048u) ? src[(gy<<11)+gx] : BIGL;
            }
        }
    }
    __syncthreads();
    int j0 = tid;
    int vy0 = j0/20, cx0 = (j0 - vy0*20)*4;
    int off0 = (1 + vy0)*CC_STRIDE + 4 + cx0;
    int j1 = tid + 1024;
    int vy1 = j1/20, cx1 = (j1 - vy1*20)*4;
    int off1 = (1 + vy1)*CC_STRIDE + 4 + cx1;
    bool has1 = (j1 < 1600);
    int* cur = A; int* nxt = B;
    for (int s = 1; s <= 8; s++){
        int changed = 0;
        if (vy0 >= s && vy0 <= 79-s && cx0+3 >= s && cx0 <= 79-s) changed |= cc_step(cur, nxt, off0);
        if (has1 && vy1 >= s && vy1 <= 79-s && cx1+3 >= s && cx1 <= 79-s) changed |= cc_step(cur, nxt, off1);
        if (!__syncthreads_or(changed)) break;
        int* t = cur; cur = nxt; nxt = t;
    }
    int row = tid >> 4, c16 = tid & 15;
    int soff = (9 + row)*CC_STRIDE + 12 + c16*4;
    int gy = blockIdx.y*64 + row, gx = blockIdx.x*64 + c16*4;
    *(int4*)(dst + (gy<<11) + gx) = *(const int4*)(cur + soff);
}

// ---------------- histogram ----------------
__global__ void k_zero_counts(){
    int i = blockIdx.x*1024 + threadIdx.x;
    if (i < NLBL) g_counts[i] = 0;
}
__global__ void k_count(){
    int p4 = (blockIdx.x*256 + threadIdx.x)*4;
    int4 l = *(const int4*)(g_labA + p4);
    #pragma unroll
    for (int k = 0; k < 4; k++){
        int lab = (k==0) ? l.x : (k==1) ? l.y : (k==2) ? l.z : l.w;
        unsigned mk = __match_any_sync(0xffffffffu, lab);
        int leader = __ffs(mk) - 1;
        if ((threadIdx.x & 31) == leader && lab != BIGL)
            atomicAdd(&g_counts[lab], __popc(mk));
    }
}

// ---------------- exact top-16 (count desc, label asc): two-stage ----------------
__global__ void k_topA(){
    __shared__ unsigned long long s[256*16];
    int chunk = (NLBL + NBLK_TOP - 1)/NBLK_TOP;
    int lo = blockIdx.x*chunk;
    int hi = min(NLBL, lo + chunk);
    unsigned long long best[16];
    #pragma unroll
    for (int i = 0; i < 16; i++) best[i] = 0ull;
    unsigned long long bmin = 0ull; int bpos = 0;
    for (int i = lo + threadIdx.x; i < hi; i += 256){
        unsigned long long key = ((unsigned long long)(unsigned)g_counts[i] << 32)
                               | (unsigned)(~(unsigned)i);
        if (key > bmin){
            best[bpos] = key;
            bmin = best[0]; bpos = 0;
            #pragma unroll
            for (int j = 1; j < 16; j++) if (best[j] < bmin){ bmin = best[j]; bpos = j; }
        }
    }
    for (int j = 0; j < 16; j++) s[threadIdx.x*16 + j] = best[j];
    __syncthreads();
    if (threadIdx.x < 32){
        for (int r = 0; r < 16; r++){
            unsigned long long m = 0ull; int mp = -1;
            for (int i = threadIdx.x; i < 4096; i += 32){
                unsigned long long v = s[i];
                if (v > m){ m = v; mp = i; }
            }
            for (int off = 16; off; off >>= 1){
                unsigned long long om = __shfl_down_sync(0xffffffffu, m, off);
                int op = __shfl_down_sync(0xffffffffu, mp, off);
                if (om > m){ m = om; mp = op; }
            }
            m  = __shfl_sync(0xffffffffu, m, 0);
            mp = __shfl_sync(0xffffffffu, mp, 0);
            if (threadIdx.x == 0){
                g_cand[blockIdx.x*16 + r] = m;
                if (mp >= 0) s[mp] = 0ull;
            }
            __syncwarp();
        }
    }
}
__global__ void k_topB(){
    __shared__ unsigned long long s[2048];
    int tid = threadIdx.x;
    for (int i = tid; i < 2048; i += 256) s[i] = (i < NBLK_TOP*16) ? g_cand[i] : 0ull;
    __syncthreads();
    if (tid < 32){
        for (int r = 0; r < 16; r++){
            unsigned long long m = 0ull; int mp = -1;
            for (int i = tid; i < 2048; i += 32){
                unsigned long long v = s[i];
                if (v > m){ m = v; mp = i; }
            }
            for (int off = 16; off; off >>= 1){
                unsigned long long om = __shfl_down_sync(0xffffffffu, m, off);
                int op = __shfl_down_sync(0xffffffffu, mp, off);
                if (om > m){ m = om; mp = op; }
            }
            m  = __shfl_sync(0xffffffffu, m, 0);
            mp = __shfl_sync(0xffffffffu, mp, 0);
            if (tid == 0){
                g_cnts[r] = (int)(m >> 32);
                g_lids[r] = (int)(~(unsigned)(m & 0xffffffffull));
                if (mp >= 0) s[mp] = 0ull;
            }
            __syncwarp();
        }
    }
}

// ---------------- bounding boxes ----------------
__global__ void k_bbinit(){
    int k = threadIdx.x;
    if (k < 16){ g_bbox[k][0] = 0x7FFFFFFF; g_bbox[k][1] = -1; g_bbox[k][2] = 0x7FFFFFFF; g_bbox[k][3] = -1; }
}
__global__ void k_bbox(){
    __shared__ int slid[16];
    __shared__ int sbb[16][4];
    int tid = threadIdx.x;
    if (tid < 16){
        slid[tid] = g_lids[tid];
        sbb[tid][0] = 0x7FFFFFFF; sbb[tid][1] = -1; sbb[tid][2] = 0x7FFFFFFF; sbb[tid][3] = -1;
    }
    __syncthreads();
    int base = blockIdx.x*1024;
    for (int q = 0; q < 4; q++){
        int p = base + q*256 + tid;
        int l = g_labA[p];
        if (l != BIGL){
            int y = p >> 11, x = p & 2047;
            #pragma unroll
            for (int k = 0; k < 16; k++) if (l == slid[k]){
                if (y < sbb[k][0]) atomicMin(&sbb[k][0], y);
                if (y > sbb[k][1]) atomicMax(&sbb[k][1], y);
                if (x < sbb[k][2]) atomicMin(&sbb[k][2], x);
                if (x > sbb[k][3]) atomicMax(&sbb[k][3], x);
            }
        }
    }
    __syncthreads();
    if (tid < 16 && sbb[tid][0] != 0x7FFFFFFF){
        atomicMin(&g_bbox[tid][0], sbb[tid][0]);
        atomicMax(&g_bbox[tid][1], sbb[tid][1]);
        atomicMin(&g_bbox[tid][2], sbb[tid][2]);
        atomicMax(&g_bbox[tid][3], sbb[tid][3]);
    }
}

// ---------------- ROI bilinear resize (227x227) ----------------
__global__ void k_roi(const float* __restrict__ img){
    int k = blockIdx.x;
    int y0 = g_bbox[k][0], y1 = g_bbox[k][1], x0 = g_bbox[k][2], x1 = g_bbox[k][3];
    if (y0 == 0x7FFFFFFF){ y0 = 0; y1 = 2047; x0 = 0; x1 = 2047; }
    float dy = (float)(y1 - y0), dx = (float)(x1 - x0);
    for (int idx = threadIdx.x; idx < 227*227; idx += blockDim.x){
        int i = idx/227, j = idx%227;
        float gy = (float)y0 + ((float)i/226.0f)*dy;
        float gx = (float)x0 + ((float)j/226.0f)*dx;
        int yf = min(max((int)floorf(gy), 0), 2046);
        int xf = min(max((int)floorf(gx), 0), 2046);
        float fy = gy - (float)yf, fx = gx - (float)xf;
        const float* r0 = img + (yf<<11) + xf;
        float v00 = r0[0], v01 = r0[1], v10 = r0[2048], v11 = r0[2049];
        g_roi[k*51529 + idx] = (1.f-fy)*((1.f-fx)*v00 + fx*v01) + fy*((1.f-fx)*v10 + fx*v11);
    }
}

// ---------------- classifier conv1: 7x7 s4 VALID, 1->16, relu ----------------
__global__ void k_c1(const float* __restrict__ cw1){
    __shared__ float sw[784];
    int tid = threadIdx.x;
    for (int i = tid; i < 784; i += 256) sw[i] = cw1[i];
    __syncthreads();
    int o = blockIdx.x*256 + tid;
    int k = o/50176, r = o%50176, oc = r/3136, s = r%3136, oy = s/56, ox = s%56;
    const float* roi = g_roi + k*51529;
    const float* wb = sw + oc*49;
    float a = 0.f;
    #pragma unroll
    for (int ky = 0; ky < 7; ky++){
        const float* rr = roi + (oy*4+ky)*227 + ox*4;
        #pragma unroll
        for (int kx = 0; kx < 7; kx++) a += rr[kx]*wb[ky*7+kx];
    }
    g_h1[o] = fmaxf(a, 0.f);
}

// ---------------- classifier conv2: 3x3 s2 VALID, 16->32, relu ----------------
__global__ void k_c2(const float* __restrict__ cw2){
    __shared__ float sw[4608];
    int tid = threadIdx.x;
    for (int i = tid; i < 4608; i += 256) sw[i] = cw2[i];
    __syncthreads();
    int o = blockIdx.x*256 + tid;
    int k = o/23328, r = o%23328, oc = r/729, s = r%729, oy = s/27, ox = s%27;
    const float* h = g_h1 + (size_t)k*16*3136;
    float a = 0.f;
    for (int ic = 0; ic < 16; ic++){
        const float* hb = h + ic*3136 + (oy*2)*56 + ox*2;
        const float* wb = sw + (oc*16+ic)*9;
        #pragma unroll
        for (int ky = 0; ky < 3; ky++)
            #pragma unroll
            for (int kx = 0; kx < 3; kx++)
                a += hb[ky*56+kx]*wb[ky*3+kx];
    }
    g_h2[o] = fmaxf(a, 0.f);
}

// ---------------- global mean + fc + argmax ----------------
__global__ void k_cls(const float* __restrict__ fc){
    __shared__ float ssum[32];
    int k = blockIdx.x;
    int tid = threadIdx.x, w = tid >> 5, lane = tid & 31;
    for (int oc = w*4; oc < w*4+4; oc++){
        float s = 0.f;
        const float* h = g_h2 + ((size_t)(k*32+oc))*729;
        for (int i = lane; i < 729; i += 32) s += h[i];
        for (int off = 16; off; off >>= 1) s += __shfl_down_sync(0xffffffffu, s, off);
        if (lane == 0) ssum[oc] = s;
    }
    __syncthreads();
    if (tid == 0){
        float best = -1e30f; int bc = 0;
        for (int c = 0; c < 4; c++){
            float lg = 0.f;
            for (int oc = 0; oc < 32; oc++) lg += (ssum[oc]*(1.0f/729.0f))*fc[oc*4+c];
            if (lg > best){ best = lg; bc = c; }
        }
        g_cls[k] = bc;
    }
}

// ---------------- final mask composition (vectorized) ----------------
__global__ void k_final(float* __restrict__ out){
    __shared__ int slid[16], scls[16];
    int tid = threadIdx.x;
    if (tid < 16){
        slid[tid] = (g_cnts[tid] >= MINSZ) ? g_lids[tid] : -1;
        scls[tid] = g_cls[tid];
    }
    __syncthreads();
    int p4 = (blockIdx.x*256 + tid)*4;
    int4 l = *(const int4*)(g_labA + p4);
    int c0 = -1, c1 = -1, c2 = -1, c3 = -1;
    #pragma unroll
    for (int k = 0; k < 16; k++){
        int lid = slid[k], cc = scls[k];
        if (l.x == lid) c0 = cc;
        if (l.y == lid) c1 = cc;
        if (l.z == lid) c2 = cc;
        if (l.w == lid) c3 = cc;
    }
    #pragma unroll
    for (int ch = 0; ch < 4; ch++){
        float4 o;
        o.x = (c0 == ch) ? 1.f : 0.f;
        o.y = (c1 == ch) ? 1.f : 0.f;
        o.z = (c2 == ch) ? 1.f : 0.f;
        o.w = (c3 == ch) ? 1.f : 0.f;
        *(float4*)(out + (size_t)ch*NPIX + p4) = o;
    }
}

// ---------------- launch ----------------
extern "C" void kernel_launch(void* const* d_in, const int* in_sizes, int n_in,
                              void* d_out, int out_size){
    const float *x = nullptr, *w1 = nullptr, *w2 = nullptr, *w3 = nullptr;
    const float *cw1 = nullptr, *cw2 = nullptr, *fc = nullptr;
    for (int i = 0; i < n_in; i++){
        switch (in_sizes[i]){
            case 4194304: x   = (const float*)d_in[i]; break;
            case 288:     w1  = (const float*)d_in[i]; break;
            case 9216:    w2  = (const float*)d_in[i]; break;
            case 32:      w3  = (const float*)d_in[i]; break;
            case 784:     cw1 = (const float*)d_in[i]; break;
            case 4608:    cw2 = (const float*)d_in[i]; break;
            case 128:     fc  = (const float*)d_in[i]; break;
            default: break;
        }
    }
    float* out = (float*)d_out;

    cudaFuncSetAttribute(k_conv_wino, cudaFuncAttributeMaxDynamicSharedMemorySize, W_TOTAL);
    cudaFuncSetAttribute(k_cc, cudaFuncAttributeMaxDynamicSharedMemorySize, CC_SMEM);

    k_uw<<<1, 1024>>>(w2);
    k_conv_wino<<<dim3(128,128), 256, W_TOTAL>>>(x, w1, w3);

    int* la = nullptr; int* lb = nullptr;
    cudaGetSymbolAddress((void**)&la, g_labA);
    cudaGetSymbolAddress((void**)&lb, g_labB);
    for (int i = 0; i < 4; i++){
        k_cc<<<dim3(32,32), 1024, CC_SMEM>>>(la, lb);
        k_cc<<<dim3(32,32), 1024, CC_SMEM>>>(lb, la);
    }

    k_zero_counts<<<(NLBL+1023)/1024, 1024>>>();
    k_count<<<NPIX/1024, 256>>>();
    k_topA<<<NBLK_TOP, 256>>>();
    k_topB<<<1, 256>>>();

    k_bbinit<<<1, 16>>>();
    k_bbox<<<NPIX/1024, 256>>>();

    k_roi<<<16, 256>>>(x);
    k_c1<<<802816/256, 256>>>(cw1);
    k_c2<<<373248/256, 256>>>(cw2);
    k_cls<<<16, 256>>>(fc);

    k_final<<<NPIX/1024, 256>>>(out);
}

// round 15
// speedup vs baseline: 2.2053x; 2.2053x over previous
#include <cuda_runtime.h>
#include <cstdint>

#define Hh 2048
#define Ww 2048
#define NPIX (Hh*Ww)            // 4194304
#define BIGL NPIX               // background label
#define NLBL (NPIX+1)
#define KTOP 16
#define NBLK_TOP 120
#define MINSZ 64

// ---------------- device scratch (no allocations allowed) ----------------
__device__ int   g_labA[NPIX];
__device__ int   g_labB[NPIX];
__device__ int   g_counts[NLBL];
__device__ unsigned long long g_cand[NBLK_TOP*KTOP];
__device__ int   g_lids[KTOP];
__device__ int   g_cnts[KTOP];
__device__ int   g_bbox[KTOP][4];
__device__ int   g_cls[KTOP];
__device__ float g_roi[KTOP*227*227];
__device__ float g_h1[KTOP*16*56*56];
__device__ float g_h2[KTOP*32*27*27];

// ---------------- helpers ----------------
__device__ __forceinline__ unsigned long long pack2(float v){
    unsigned long long r; asm("mov.b64 %0, {%1, %1};" : "=l"(r) : "f"(v)); return r;
}
__device__ __forceinline__ void fma2(unsigned long long& a, unsigned long long v, unsigned long long w){
    asm("fma.rn.f32x2 %0, %1, %2, %0;" : "+l"(a) : "l"(v), "l"(w));
}
__device__ __forceinline__ float2 unpack2(unsigned long long a){
    float2 f; asm("mov.b64 {%0, %1}, %2;" : "=f"(f.x), "=f"(f.y) : "l"(a)); return f;
}
__device__ __forceinline__ unsigned f2tf(float v){
    unsigned u; asm("cvt.rna.tf32.f32 %0, %1;" : "=r"(u) : "f"(v)); return u;
}
__device__ __forceinline__ void mma8(float* d, unsigned a0, unsigned a1, unsigned a2, unsigned a3,
                                     unsigned b0, unsigned b1){
    asm volatile("mma.sync.aligned.m16n8k8.row.col.f32.tf32.tf32.f32 "
        "{%0,%1,%2,%3}, {%4,%5,%6,%7}, {%8,%9}, {%0,%1,%2,%3};"
        : "+f"(d[0]), "+f"(d[1]), "+f"(d[2]), "+f"(d[3])
        : "r"(a0), "r"(a1), "r"(a2), "r"(a3), "r"(b0), "r"(b1));
}

// ================= conv via mma.sync tf32 (3xTF32 fp32 emulation) — verbatim R9 =================
#define ICP 10
#define OF_AHI 0
#define OF_ALO 11560
#define OF_B   23120
#define OF_X   41552
#define OF_W1  42884
#define OF_W3  43172
#define CONV_SMEM (43204*4)   // 172816 B

__global__ void __launch_bounds__(256) k_conv_tc(const float* __restrict__ x,
                                                 const float* __restrict__ w1,
                                                 const float* __restrict__ w2,
                                                 const float* __restrict__ w3){
    extern __shared__ float sm[];
    float*  sAhi = sm + OF_AHI;
    float*  sAlo = sm + OF_ALO;
    float2* sB   = (float2*)(sm + OF_B);
    float*  sX   = sm + OF_X;
    float*  sW1  = sm + OF_W1;
    float*  sW3  = sm + OF_W3;

    int tid = threadIdx.x;
    int wid = tid >> 5, lane = tid & 31;
    int lq = lane >> 2, lc = lane & 3;

    for (int i = tid; i < 288; i += 256){
        int tap = i >> 5, oc = i & 31;
        sW1[i] = w1[oc*9 + tap];
    }
    if (tid < 32) sW3[tid] = w3[tid];

    for (int i = tid; i < 4608; i += 256){
        int c = i & 3, n = (i >> 2) & 7, nt = (i >> 5) & 3, g = (i >> 7) & 3, t = i >> 9;
        int oc = nt*8 + n, ic = g*8 + 2*c;
        float wa = w2[((size_t)oc*32 + ic)*9 + t];
        float wb = w2[((size_t)oc*32 + ic + 1)*9 + t];
        unsigned ha = f2tf(wa), hb = f2tf(wb);
        float la = wa - __uint_as_float(ha), lb = wb - __uint_as_float(hb);
        sB[i]        = make_float2(__uint_as_float(ha), __uint_as_float(hb));
        sB[4608 + i] = make_float2(__uint_as_float(f2tf(la)), __uint_as_float(f2tf(lb)));
    }

    int bx0 = blockIdx.x*32, by0 = blockIdx.y*32;
    for (int i = tid; i < 1296; i += 256){
        int r = i/36, cxx = i - r*36;
        int gy = by0 - 2 + r, gx = bx0 - 2 + cxx;
        float v = 0.f;
        if ((unsigned)gy < 2048u && (unsigned)gx < 2048u) v = x[(gy<<11)+gx];
        sX[r*37 + cxx] = v;
    }
    __syncthreads();

    float d[128];
    #pragma unroll
    for (int i = 0; i < 128; i++) d[i] = 0.f;

    const unsigned long long* w1u = (const unsigned long long*)sW1;

    for (int g = 0; g < 4; g++){
        if (g) __syncthreads();
        for (int i = tid; i < 1156; i += 256){
            int fy = i/34, fx = i - fy*34;
            const float* base = sX + fy*37 + fx;
            unsigned long long vp[9];
            #pragma unroll
            for (int r = 0; r < 3; r++)
                #pragma unroll
                for (int c = 0; c < 3; c++) vp[r*3+c] = pack2(base[r*37+c]);
            int ao = i*ICP;
            #pragma unroll
            for (int q = 0; q < 4; q++){
                unsigned long long a = 0ull;
                #pragma unroll
                for (int t = 0; t < 9; t++) fma2(a, vp[t], w1u[t*16 + g*4 + q]);
                float2 f = unpack2(a);
                float v0 = fmaxf(f.x, 0.f), v1 = fmaxf(f.y, 0.f);
                unsigned h0 = f2tf(v0), h1 = f2tf(v1);
                float l0 = v0 - __uint_as_float(h0), l1 = v1 - __uint_as_float(h1);
                *(float2*)(sAhi + ao + 2*q) = make_float2(__uint_as_float(h0), __uint_as_float(h1));
                *(float2*)(sAlo + ao + 2*q) = make_float2(__uint_as_float(f2tf(l0)), __uint_as_float(f2tf(l1)));
            }
        }
        __syncthreads();

        for (int t = 0; t < 9; t++){
            int dy = t/3, dx = t - dy*3;
            unsigned bh[8], bl[8];
            #pragma unroll
            for (int nt = 0; nt < 4; nt++){
                int bi = (((t*4 + g)*4 + nt)*8 + lq)*4 + lc;
                float2 bv = sB[bi];
                bh[2*nt] = __float_as_uint(bv.x); bh[2*nt+1] = __float_as_uint(bv.y);
                float2 bw = sB[4608 + bi];
                bl[2*nt] = __float_as_uint(bw.x); bl[2*nt+1] = __float_as_uint(bw.y);
            }
            int base0 = ((4*wid + dy)*34 + lq + dx)*ICP + lc*2;
            #pragma unroll
            for (int mt = 0; mt < 8; mt++){
                int off = base0 + (mt>>1)*(34*ICP) + (mt&1)*(16*ICP);
                float2 ah0 = *(const float2*)(sAhi + off);
                float2 ah1 = *(const float2*)(sAhi + off + 8*ICP);
                float2 al0 = *(const float2*)(sAlo + off);
                float2 al1 = *(const float2*)(sAlo + off + 8*ICP);
                unsigned a0h = __float_as_uint(ah0.x), a1h = __float_as_uint(ah1.x);
                unsigned a2h = __float_as_uint(ah0.y), a3h = __float_as_uint(ah1.y);
                unsigned a0l = __float_as_uint(al0.x), a1l = __float_as_uint(al1.x);
                unsigned a2l = __float_as_uint(al0.y), a3l = __float_as_uint(al1.y);
                #pragma unroll
                for (int nt = 0; nt < 4; nt++){
                    float* dd = d + (mt*4 + nt)*4;
                    mma8(dd, a0h, a1h, a2h, a3h, bh[2*nt], bh[2*nt+1]);
                    mma8(dd, a0h, a1h, a2h, a3h, bl[2*nt], bl[2*nt+1]);
                    mma8(dd, a0l, a1l, a2l, a3l, bh[2*nt], bh[2*nt+1]);
                }
            }
        }
    }

    #pragma unroll
    for (int mt = 0; mt < 8; mt++){
        float z0 = 0.f, z1 = 0.f;
        #pragma unroll
        for (int nt = 0; nt < 4; nt++){
            const float* dd = d + (mt*4 + nt)*4;
            float wl = sW3[nt*8 + 2*lc], wh = sW3[nt*8 + 2*lc + 1];
            z0 += fmaxf(dd[0], 0.f)*wl; z0 += fmaxf(dd[1], 0.f)*wh;
            z1 += fmaxf(dd[2], 0.f)*wl; z1 += fmaxf(dd[3], 0.f)*wh;
        }
        z0 += __shfl_xor_sync(0xffffffffu, z0, 1);
        z0 += __shfl_xor_sync(0xffffffffu, z0, 2);
        z1 += __shfl_xor_sync(0xffffffffu, z1, 1);
        z1 += __shfl_xor_sync(0xffffffffu, z1, 2);
        if (lc == 0){
            int y  = by0 + 4*wid + (mt>>1);
            int x0 = bx0 + (mt&1)*16 + lq;
            int p0 = (y<<11) + x0;
            int p1 = p0 + 8;
            g_labA[p0] = (z0 > 0.f) ? p0 : BIGL;
            g_labA[p1] = (z1 > 0.f) ? p1 : BIGL;
        }
    }
}

// ================= connected components: 2 launches x 32 exact Jacobi steps =================
// interior 64x64, halo 32 -> region 128x128 valid at tile rows 1..128, cols 4..131.
// stride 140, 130 rows; sentinel ring = BIGL. Step s computes only [s,127-s]^2; early-exit
// when a full step changes nothing (monotone min-propagation, windows shrink).
#define CC_STRIDE 140
#define CC_CELLS  (130*CC_STRIDE)    // 18200
#define CC_SMEM   (2*CC_CELLS*4)     // 145600 B

__device__ __forceinline__ int cc_step(const int* __restrict__ cur, int* __restrict__ nxt, int off){
    int4 c = *(const int4*)(cur + off);
    int4 u = *(const int4*)(cur + off - CC_STRIDE);
    int4 d = *(const int4*)(cur + off + CC_STRIDE);
    int l = cur[off-1], r = cur[off+4];
    int4 o; int m;
    m = min(min(u.x,d.x), min(l,   c.y)); o.x = (c.x==BIGL) ? BIGL : min(c.x, m);
    m = min(min(u.y,d.y), min(c.x, c.z)); o.y = (c.y==BIGL) ? BIGL : min(c.y, m);
    m = min(min(u.z,d.z), min(c.y, c.w)); o.z = (c.z==BIGL) ? BIGL : min(c.z, m);
    m = min(min(u.w,d.w), min(c.z, r  )); o.w = (c.w==BIGL) ? BIGL : min(c.w, m);
    *(int4*)(nxt + off) = o;
    return (o.x^c.x) | (o.y^c.y) | (o.z^c.z) | (o.w^c.w);
}

__global__ __launch_bounds__(1024) void k_cc(const int* __restrict__ src, int* __restrict__ dst){
    extern __shared__ int sh[];
    int* A = sh;
    int* B = sh + CC_CELLS;
    int tid = threadIdx.x;
    int gx0 = blockIdx.x*64 - 32, gy0 = blockIdx.y*64 - 32;

    for (int s = tid; s < CC_CELLS; s += 1024){ A[s] = BIGL; B[s] = BIGL; }
    __syncthreads();

    // load 128x128 region (int4 fast path), rows gy0..gy0+127, cols gx0..gx0+127
    #pragma unroll
    for (int k = 0; k < 4; k++){
        int v = tid + k*1024;                    // 0..4095
        int vy = v >> 5, vx = (v & 31)*4;
        int gy = gy0 + vy, gxb = gx0 + vx;
        int off = (1+vy)*CC_STRIDE + 4 + vx;
        if ((unsigned)gy < 2048u){
            if (gxb >= 0 && gxb + 3 < 2048){
                *(int4*)(A + off) = *(const int4*)(src + (gy<<11) + gxb);
            } else {
                #pragma unroll
                for (int e = 0; e < 4; e++){
                    int gx = gxb + e;
                    A[off+e] = ((unsigned)gx < 2048u) ? src[(gy<<11)+gx] : BIGL;
                }
            }
        }
    }
    __syncthreads();

    // 4 int4 cells per thread (region coords)
    int vy0 = tid >> 5,          cx0 = (tid & 31)*4;
    int off0 = (1 + vy0)*CC_STRIDE + 4 + cx0;
    int vy1 = vy0 + 32;
    int off1 = off0 + 32*CC_STRIDE;
    int vy2 = vy0 + 64;
    int off2 = off0 + 64*CC_STRIDE;
    int vy3 = vy0 + 96;
    int off3 = off0 + 96*CC_STRIDE;

    int* cur = A; int* nxt = B;
    for (int s = 1; s <= 32; s++){
        int changed = 0;
        bool cok = (cx0+3 >= s) && (cx0 <= 127-s);
        if (cok){
            if (vy0 >= s && vy0 <= 127-s) changed |= cc_step(cur, nxt, off0);
            if (vy1 >= s && vy1 <= 127-s) changed |= cc_step(cur, nxt, off1);
            if (vy2 >= s && vy2 <= 127-s) changed |= cc_step(cur, nxt, off2);
            if (vy3 >= s && vy3 <= 127-s) changed |= cc_step(cur, nxt, off3);
        }
        if (!__syncthreads_or(changed)) break;
        int* t = cur; cur = nxt; nxt = t;
    }

    // write interior 64x64: region (32,32) -> tile (33, 36)
    int row = tid >> 4, c16 = tid & 15;
    int soff = (33 + row)*CC_STRIDE + 36 + c16*4;
    int gy = blockIdx.y*64 + row, gx = blockIdx.x*64 + c16*4;
    *(int4*)(dst + (gy<<11) + gx) = *(const int4*)(cur + soff);
}

// ---------------- histogram (bbinit folded in) ----------------
__global__ void k_zero_counts(){
    int i = blockIdx.x*1024 + threadIdx.x;
    if (i < NLBL) g_counts[i] = 0;
    if (blockIdx.x == 0 && threadIdx.x < 16){
        g_bbox[threadIdx.x][0] = 0x7FFFFFFF; g_bbox[threadIdx.x][1] = -1;
        g_bbox[threadIdx.x][2] = 0x7FFFFFFF; g_bbox[threadIdx.x][3] = -1;
    }
}
__global__ void k_count(){
    int p4 = (blockIdx.x*256 + threadIdx.x)*4;
    int4 l = *(const int4*)(g_labA + p4);
    #pragma unroll
    for (int k = 0; k < 4; k++){
        int lab = (k==0) ? l.x : (k==1) ? l.y : (k==2) ? l.z : l.w;
        unsigned mk = __match_any_sync(0xffffffffu, lab);
        int leader = __ffs(mk) - 1;
        if ((threadIdx.x & 31) == leader && lab != BIGL)
            atomicAdd(&g_counts[lab], __popc(mk));
    }
}

// ---------------- exact top-16 (count desc, label asc): two-stage ----------------
__global__ void k_topA(){
    __shared__ unsigned long long s[256*16];
    int chunk = (NLBL + NBLK_TOP - 1)/NBLK_TOP;
    int lo = blockIdx.x*chunk;
    int hi = min(NLBL, lo + chunk);
    unsigned long long best[16];
    #pragma unroll
    for (int i = 0; i < 16; i++) best[i] = 0ull;
    unsigned long long bmin = 0ull; int bpos = 0;
    for (int i = lo + threadIdx.x; i < hi; i += 256){
        unsigned long long key = ((unsigned long long)(unsigned)g_counts[i] << 32)
                               | (unsigned)(~(unsigned)i);
        if (key > bmin){
            best[bpos] = key;
            bmin = best[0]; bpos = 0;
            #pragma unroll
            for (int j = 1; j < 16; j++) if (best[j] < bmin){ bmin = best[j]; bpos = j; }
        }
    }
    for (int j = 0; j < 16; j++) s[threadIdx.x*16 + j] = best[j];
    __syncthreads();
    if (threadIdx.x < 32){
        for (int r = 0; r < 16; r++){
            unsigned long long m = 0ull; int mp = -1;
            for (int i = threadIdx.x; i < 4096; i += 32){
                unsigned long long v = s[i];
                if (v > m){ m = v; mp = i; }
            }
            for (int off = 16; off; off >>= 1){
                unsigned long long om = __shfl_down_sync(0xffffffffu, m, off);
                int op = __shfl_down_sync(0xffffffffu, mp, off);
                if (om > m){ m = om; mp = op; }
            }
            m  = __shfl_sync(0xffffffffu, m, 0);
            mp = __shfl_sync(0xffffffffu, mp, 0);
            if (threadIdx.x == 0){
                g_cand[blockIdx.x*16 + r] = m;
                if (mp >= 0) s[mp] = 0ull;
            }
            __syncwarp();
        }
    }
}
__global__ void k_topB(){
    __shared__ unsigned long long s[2048];
    int tid = threadIdx.x;
    for (int i = tid; i < 2048; i += 256) s[i] = (i < NBLK_TOP*16) ? g_cand[i] : 0ull;
    __syncthreads();
    if (tid < 32){
        for (int r = 0; r < 16; r++){
            unsigned long long m = 0ull; int mp = -1;
            for (int i = tid; i < 2048; i += 32){
                unsigned long long v = s[i];
                if (v > m){ m = v; mp = i; }
            }
            for (int off = 16; off; off >>= 1){
                unsigned long long om = __shfl_down_sync(0xffffffffu, m, off);
                int op = __shfl_down_sync(0xffffffffu, mp, off);
                if (om > m){ m = om; mp = op; }
            }
            m  = __shfl_sync(0xffffffffu, m, 0);
            mp = __shfl_sync(0xffffffffu, mp, 0);
            if (tid == 0){
                g_cnts[r] = (int)(m >> 32);
                g_lids[r] = (int)(~(unsigned)(m & 0xffffffffull));
                if (mp >= 0) s[mp] = 0ull;
            }
            __syncwarp();
        }
    }
}

// ---------------- bounding boxes ----------------
__global__ void k_bbox(){
    __shared__ int slid[16];
    __shared__ int sbb[16][4];
    int tid = threadIdx.x;
    if (tid < 16){
        slid[tid] = g_lids[tid];
        sbb[tid][0] = 0x7FFFFFFF; sbb[tid][1] = -1; sbb[tid][2] = 0x7FFFFFFF; sbb[tid][3] = -1;
    }
    __syncthreads();
    int base = blockIdx.x*1024;
    for (int q = 0; q < 4; q++){
        int p = base + q*256 + tid;
        int l = g_labA[p];
        if (l != BIGL){
            int y = p >> 11, x = p & 2047;
            #pragma unroll
            for (int k = 0; k < 16; k++) if (l == slid[k]){
                if (y < sbb[k][0]) atomicMin(&sbb[k][0], y);
                if (y > sbb[k][1]) atomicMax(&sbb[k][1], y);
                if (x < sbb[k][2]) atomicMin(&sbb[k][2], x);
                if (x > sbb[k][3]) atomicMax(&sbb[k][3], x);
            }
        }
    }
    __syncthreads();
    if (tid < 16 && sbb[tid][0] != 0x7FFFFFFF){
        atomicMin(&g_bbox[tid][0], sbb[tid][0]);
        atomicMax(&g_bbox[tid][1], sbb[tid][1]);
        atomicMin(&g_bbox[tid][2], sbb[tid][2]);
        atomicMax(&g_bbox[tid][3], sbb[tid][3]);
    }
}

// ---------------- ROI bilinear resize (227x227) ----------------
__global__ void k_roi(const float* __restrict__ img){
    int k = blockIdx.x;
    int y0 = g_bbox[k][0], y1 = g_bbox[k][1], x0 = g_bbox[k][2], x1 = g_bbox[k][3];
    if (y0 == 0x7FFFFFFF){ y0 = 0; y1 = 2047; x0 = 0; x1 = 2047; }
    float dy = (float)(y1 - y0), dx = (float)(x1 - x0);
    for (int idx = threadIdx.x; idx < 227*227; idx += blockDim.x){
        int i = idx/227, j = idx%227;
        float gy = (float)y0 + ((float)i/226.0f)*dy;
        float gx = (float)x0 + ((float)j/226.0f)*dx;
        int yf = min(max((int)floorf(gy), 0), 2046);
        int xf = min(max((int)floorf(gx), 0), 2046);
        float fy = gy - (float)yf, fx = gx - (float)xf;
        const float* r0 = img + (yf<<11) + xf;
        float v00 = r0[0], v01 = r0[1], v10 = r0[2048], v11 = r0[2049];
        g_roi[k*51529 + idx] = (1.f-fy)*((1.f-fx)*v00 + fx*v01) + fy*((1.f-fx)*v10 + fx*v11);
    }
}

// ---------------- classifier conv1: 7x7 s4 VALID, 1->16, relu ----------------
__global__ void k_c1(const float* __restrict__ cw1){
    __shared__ float sw[784];
    int tid = threadIdx.x;
    for (int i = tid; i < 784; i += 256) sw[i] = cw1[i];
    __syncthreads();
    int o = blockIdx.x*256 + tid;
    int k = o/50176, r = o%50176, oc = r/3136, s = r%3136, oy = s/56, ox = s%56;
    const float* roi = g_roi + k*51529;
    const float* wb = sw + oc*49;
    float a = 0.f;
    #pragma unroll
    for (int ky = 0; ky < 7; ky++){
        const float* rr = roi + (oy*4+ky)*227 + ox*4;
        #pragma unroll
        for (int kx = 0; kx < 7; kx++) a += rr[kx]*wb[ky*7+kx];
    }
    g_h1[o] = fmaxf(a, 0.f);
}

// ---------------- classifier conv2: 3x3 s2 VALID, 16->32, relu ----------------
__global__ void k_c2(const float* __restrict__ cw2){
    __shared__ float sw[4608];
    int tid = threadIdx.x;
    for (int i = tid; i < 4608; i += 256) sw[i] = cw2[i];
    __syncthreads();
    int o = blockIdx.x*256 + tid;
    int k = o/23328, r = o%23328, oc = r/729, s = r%729, oy = s/27, ox = s%27;
    const float* h = g_h1 + (size_t)k*16*3136;
    float a = 0.f;
    for (int ic = 0; ic < 16; ic++){
        const float* hb = h + ic*3136 + (oy*2)*56 + ox*2;
        const float* wb = sw + (oc*16+ic)*9;
        #pragma unroll
        for (int ky = 0; ky < 3; ky++)
            #pragma unroll
            for (int kx = 0; kx < 3; kx++)
                a += hb[ky*56+kx]*wb[ky*3+kx];
    }
    g_h2[o] = fmaxf(a, 0.f);
}

// ---------------- global mean + fc + argmax ----------------
__global__ void k_cls(const float* __restrict__ fc){
    __shared__ float ssum[32];
    int k = blockIdx.x;
    int tid = threadIdx.x, w = tid >> 5, lane = tid & 31;
    for (int oc = w*4; oc < w*4+4; oc++){
        float s = 0.f;
        const float* h = g_h2 + ((size_t)(k*32+oc))*729;
        for (int i = lane; i < 729; i += 32) s += h[i];
        for (int off = 16; off; off >>= 1) s += __shfl_down_sync(0xffffffffu, s, off);
        if (lane == 0) ssum[oc] = s;
    }
    __syncthreads();
    if (tid == 0){
        float best = -1e30f; int bc = 0;
        for (int c = 0; c < 4; c++){
            float lg = 0.f;
            for (int oc = 0; oc < 32; oc++) lg += (ssum[oc]*(1.0f/729.0f))*fc[oc*4+c];
            if (lg > best){ best = lg; bc = c; }
        }
        g_cls[k] = bc;
    }
}

// ---------------- final mask composition (vectorized) ----------------
__global__ void k_final(float* __restrict__ out){
    __shared__ int slid[16], scls[16];
    int tid = threadIdx.x;
    if (tid < 16){
        slid[tid] = (g_cnts[tid] >= MINSZ) ? g_lids[tid] : -1;
        scls[tid] = g_cls[tid];
    }
    __syncthreads();
    int p4 = (blockIdx.x*256 + tid)*4;
    int4 l = *(const int4*)(g_labA + p4);
    int c0 = -1, c1 = -1, c2 = -1, c3 = -1;
    #pragma unroll
    for (int k = 0; k < 16; k++){
        int lid = slid[k], cc = scls[k];
        if (l.x == lid) c0 = cc;
        if (l.y == lid) c1 = cc;
        if (l.z == lid) c2 = cc;
        if (l.w == lid) c3 = cc;
    }
    #pragma unroll
    for (int ch = 0; ch < 4; ch++){
        float4 o;
        o.x = (c0 == ch) ? 1.f : 0.f;
        o.y = (c1 == ch) ? 1.f : 0.f;
        o.z = (c2 == ch) ? 1.f : 0.f;
        o.w = (c3 == ch) ? 1.f : 0.f;
        *(float4*)(out + (size_t)ch*NPIX + p4) = o;
    }
}

// ---------------- launch ----------------
extern "C" void kernel_launch(void* const* d_in, const int* in_sizes, int n_in,
                              void* d_out, int out_size){
    const float *x = nullptr, *w1 = nullptr, *w2 = nullptr, *w3 = nullptr;
    const float *cw1 = nullptr, *cw2 = nullptr, *fc = nullptr;
    for (int i = 0; i < n_in; i++){
        switch (in_sizes[i]){
            case 4194304: x   = (const float*)d_in[i]; break;
            case 288:     w1  = (const float*)d_in[i]; break;
            case 9216:    w2  = (const float*)d_in[i]; break;
            case 32:      w3  = (const float*)d_in[i]; break;
            case 784:     cw1 = (const float*)d_in[i]; break;
            case 4608:    cw2 = (const float*)d_in[i]; break;
            case 128:     fc  = (const float*)d_in[i]; break;
            default: break;
        }
    }
    float* out = (float*)d_out;

    cudaFuncSetAttribute(k_conv_tc, cudaFuncAttributeMaxDynamicSharedMemorySize, CONV_SMEM);
    cudaFuncSetAttribute(k_cc, cudaFuncAttributeMaxDynamicSharedMemorySize, CC_SMEM);

    k_conv_tc<<<dim3(64,64), 256, CONV_SMEM>>>(x, w1, w2, w3);

    int* la = nullptr; int* lb = nullptr;
    cudaGetSymbolAddress((void**)&la, g_labA);
    cudaGetSymbolAddress((void**)&lb, g_labB);
    k_cc<<<dim3(32,32), 1024, CC_SMEM>>>(la, lb);   // 32 steps A -> B
    k_cc<<<dim3(32,32), 1024, CC_SMEM>>>(lb, la);   // 32 steps B -> A

    k_zero_counts<<<(NLBL+1023)/1024, 1024>>>();
    k_count<<<NPIX/1024, 256>>>();
    k_topA<<<NBLK_TOP, 256>>>();
    k_topB<<<1, 256>>>();

    k_bbox<<<NPIX/1024, 256>>>();

    k_roi<<<16, 256>>>(x);
    k_c1<<<802816/256, 256>>>(cw1);
    k_c2<<<373248/256, 256>>>(cw2);
    k_cls<<<16, 256>>>(fc);

    k_final<<<NPIX/1024, 256>>>(out);
}

// round 16
// speedup vs baseline: 2.2238x; 1.0084x over previous
#include <cuda_runtime.h>
#include <cstdint>

#define Hh 2048
#define Ww 2048
#define NPIX (Hh*Ww)            // 4194304
#define BIGL NPIX               // background label
#define NLBL (NPIX+1)
#define KTOP 16
#define NBLK_TOP 120
#define MINSZ 64

// ---------------- device scratch (no allocations allowed) ----------------
__device__ int   g_labA[NPIX];
__device__ int   g_labB[NPIX];
__device__ int   g_counts[NLBL];
__device__ unsigned long long g_cand[NBLK_TOP*KTOP];
__device__ int   g_lids[KTOP];
__device__ int   g_cnts[KTOP];
__device__ int   g_bbox[KTOP][4];
__device__ int   g_cls[KTOP];
__device__ float g_roi[KTOP*227*227];
__device__ float g_h1[KTOP*16*56*56];
__device__ float g_h2[KTOP*32*27*27];

// ---------------- helpers ----------------
__device__ __forceinline__ unsigned long long pack2(float v){
    unsigned long long r; asm("mov.b64 %0, {%1, %1};" : "=l"(r) : "f"(v)); return r;
}
__device__ __forceinline__ void fma2(unsigned long long& a, unsigned long long v, unsigned long long w){
    asm("fma.rn.f32x2 %0, %1, %2, %0;" : "+l"(a) : "l"(v), "l"(w));
}
__device__ __forceinline__ float2 unpack2(unsigned long long a){
    float2 f; asm("mov.b64 {%0, %1}, %2;" : "=f"(f.x), "=f"(f.y) : "l"(a)); return f;
}
__device__ __forceinline__ unsigned f2tf(float v){
    unsigned u; asm("cvt.rna.tf32.f32 %0, %1;" : "=r"(u) : "f"(v)); return u;
}
__device__ __forceinline__ void mma8(float* d, unsigned a0, unsigned a1, unsigned a2, unsigned a3,
                                     unsigned b0, unsigned b1){
    asm volatile("mma.sync.aligned.m16n8k8.row.col.f32.tf32.tf32.f32 "
        "{%0,%1,%2,%3}, {%4,%5,%6,%7}, {%8,%9}, {%0,%1,%2,%3};"
        : "+f"(d[0]), "+f"(d[1]), "+f"(d[2]), "+f"(d[3])
        : "r"(a0), "r"(a1), "r"(a2), "r"(a3), "r"(b0), "r"(b1));
}

// ================= conv via mma.sync tf32 (3xTF32 fp32 emulation) — verbatim R9 =================
#define ICP 10
#define OF_AHI 0
#define OF_ALO 11560
#define OF_B   23120
#define OF_X   41552
#define OF_W1  42884
#define OF_W3  43172
#define CONV_SMEM (43204*4)   // 172816 B

__global__ void __launch_bounds__(256) k_conv_tc(const float* __restrict__ x,
                                                 const float* __restrict__ w1,
                                                 const float* __restrict__ w2,
                                                 const float* __restrict__ w3){
    extern __shared__ float sm[];
    float*  sAhi = sm + OF_AHI;
    float*  sAlo = sm + OF_ALO;
    float2* sB   = (float2*)(sm + OF_B);
    float*  sX   = sm + OF_X;
    float*  sW1  = sm + OF_W1;
    float*  sW3  = sm + OF_W3;

    int tid = threadIdx.x;
    int wid = tid >> 5, lane = tid & 31;
    int lq = lane >> 2, lc = lane & 3;

    for (int i = tid; i < 288; i += 256){
        int tap = i >> 5, oc = i & 31;
        sW1[i] = w1[oc*9 + tap];
    }
    if (tid < 32) sW3[tid] = w3[tid];

    for (int i = tid; i < 4608; i += 256){
        int c = i & 3, n = (i >> 2) & 7, nt = (i >> 5) & 3, g = (i >> 7) & 3, t = i >> 9;
        int oc = nt*8 + n, ic = g*8 + 2*c;
        float wa = w2[((size_t)oc*32 + ic)*9 + t];
        float wb = w2[((size_t)oc*32 + ic + 1)*9 + t];
        unsigned ha = f2tf(wa), hb = f2tf(wb);
        float la = wa - __uint_as_float(ha), lb = wb - __uint_as_float(hb);
        sB[i]        = make_float2(__uint_as_float(ha), __uint_as_float(hb));
        sB[4608 + i] = make_float2(__uint_as_float(f2tf(la)), __uint_as_float(f2tf(lb)));
    }

    int bx0 = blockIdx.x*32, by0 = blockIdx.y*32;
    for (int i = tid; i < 1296; i += 256){
        int r = i/36, cxx = i - r*36;
        int gy = by0 - 2 + r, gx = bx0 - 2 + cxx;
        float v = 0.f;
        if ((unsigned)gy < 2048u && (unsigned)gx < 2048u) v = x[(gy<<11)+gx];
        sX[r*37 + cxx] = v;
    }
    __syncthreads();

    float d[128];
    #pragma unroll
    for (int i = 0; i < 128; i++) d[i] = 0.f;

    const unsigned long long* w1u = (const unsigned long long*)sW1;

    for (int g = 0; g < 4; g++){
        if (g) __syncthreads();
        for (int i = tid; i < 1156; i += 256){
            int fy = i/34, fx = i - fy*34;
            const float* base = sX + fy*37 + fx;
            unsigned long long vp[9];
            #pragma unroll
            for (int r = 0; r < 3; r++)
                #pragma unroll
                for (int c = 0; c < 3; c++) vp[r*3+c] = pack2(base[r*37+c]);
            int ao = i*ICP;
            #pragma unroll
            for (int q = 0; q < 4; q++){
                unsigned long long a = 0ull;
                #pragma unroll
                for (int t = 0; t < 9; t++) fma2(a, vp[t], w1u[t*16 + g*4 + q]);
                float2 f = unpack2(a);
                float v0 = fmaxf(f.x, 0.f), v1 = fmaxf(f.y, 0.f);
                unsigned h0 = f2tf(v0), h1 = f2tf(v1);
                float l0 = v0 - __uint_as_float(h0), l1 = v1 - __uint_as_float(h1);
                *(float2*)(sAhi + ao + 2*q) = make_float2(__uint_as_float(h0), __uint_as_float(h1));
                *(float2*)(sAlo + ao + 2*q) = make_float2(__uint_as_float(f2tf(l0)), __uint_as_float(f2tf(l1)));
            }
        }
        __syncthreads();

        for (int t = 0; t < 9; t++){
            int dy = t/3, dx = t - dy*3;
            unsigned bh[8], bl[8];
            #pragma unroll
            for (int nt = 0; nt < 4; nt++){
                int bi = (((t*4 + g)*4 + nt)*8 + lq)*4 + lc;
                float2 bv = sB[bi];
                bh[2*nt] = __float_as_uint(bv.x); bh[2*nt+1] = __float_as_uint(bv.y);
                float2 bw = sB[4608 + bi];
                bl[2*nt] = __float_as_uint(bw.x); bl[2*nt+1] = __float_as_uint(bw.y);
            }
            int base0 = ((4*wid + dy)*34 + lq + dx)*ICP + lc*2;
            #pragma unroll
            for (int mt = 0; mt < 8; mt++){
                int off = base0 + (mt>>1)*(34*ICP) + (mt&1)*(16*ICP);
                float2 ah0 = *(const float2*)(sAhi + off);
                float2 ah1 = *(const float2*)(sAhi + off + 8*ICP);
                float2 al0 = *(const float2*)(sAlo + off);
                float2 al1 = *(const float2*)(sAlo + off + 8*ICP);
                unsigned a0h = __float_as_uint(ah0.x), a1h = __float_as_uint(ah1.x);
                unsigned a2h = __float_as_uint(ah0.y), a3h = __float_as_uint(ah1.y);
                unsigned a0l = __float_as_uint(al0.x), a1l = __float_as_uint(al1.x);
                unsigned a2l = __float_as_uint(al0.y), a3l = __float_as_uint(al1.y);
                #pragma unroll
                for (int nt = 0; nt < 4; nt++){
                    float* dd = d + (mt*4 + nt)*4;
                    mma8(dd, a0h, a1h, a2h, a3h, bh[2*nt], bh[2*nt+1]);
                    mma8(dd, a0h, a1h, a2h, a3h, bl[2*nt], bl[2*nt+1]);
                    mma8(dd, a0l, a1l, a2l, a3l, bh[2*nt], bh[2*nt+1]);
                }
            }
        }
    }

    #pragma unroll
    for (int mt = 0; mt < 8; mt++){
        float z0 = 0.f, z1 = 0.f;
        #pragma unroll
        for (int nt = 0; nt < 4; nt++){
            const float* dd = d + (mt*4 + nt)*4;
            float wl = sW3[nt*8 + 2*lc], wh = sW3[nt*8 + 2*lc + 1];
            z0 += fmaxf(dd[0], 0.f)*wl; z0 += fmaxf(dd[1], 0.f)*wh;
            z1 += fmaxf(dd[2], 0.f)*wl; z1 += fmaxf(dd[3], 0.f)*wh;
        }
        z0 += __shfl_xor_sync(0xffffffffu, z0, 1);
        z0 += __shfl_xor_sync(0xffffffffu, z0, 2);
        z1 += __shfl_xor_sync(0xffffffffu, z1, 1);
        z1 += __shfl_xor_sync(0xffffffffu, z1, 2);
        if (lc == 0){
            int y  = by0 + 4*wid + (mt>>1);
            int x0 = bx0 + (mt&1)*16 + lq;
            int p0 = (y<<11) + x0;
            int p1 = p0 + 8;
            g_labA[p0] = (z0 > 0.f) ? p0 : BIGL;
            g_labA[p1] = (z1 > 0.f) ? p1 : BIGL;
        }
    }
}

// ================= connected components: 2 launches x 32 exact Jacobi steps (R15) =================
#define CC_STRIDE 140
#define CC_CELLS  (130*CC_STRIDE)    // 18200
#define CC_SMEM   (2*CC_CELLS*4)     // 145600 B

__device__ __forceinline__ int cc_step(const int* __restrict__ cur, int* __restrict__ nxt, int off){
    int4 c = *(const int4*)(cur + off);
    int4 u = *(const int4*)(cur + off - CC_STRIDE);
    int4 d = *(const int4*)(cur + off + CC_STRIDE);
    int l = cur[off-1], r = cur[off+4];
    int4 o; int m;
    m = min(min(u.x,d.x), min(l,   c.y)); o.x = (c.x==BIGL) ? BIGL : min(c.x, m);
    m = min(min(u.y,d.y), min(c.x, c.z)); o.y = (c.y==BIGL) ? BIGL : min(c.y, m);
    m = min(min(u.z,d.z), min(c.y, c.w)); o.z = (c.z==BIGL) ? BIGL : min(c.z, m);
    m = min(min(u.w,d.w), min(c.z, r  )); o.w = (c.w==BIGL) ? BIGL : min(c.w, m);
    *(int4*)(nxt + off) = o;
    return (o.x^c.x) | (o.y^c.y) | (o.z^c.z) | (o.w^c.w);
}

__global__ __launch_bounds__(1024) void k_cc(const int* __restrict__ src, int* __restrict__ dst){
    extern __shared__ int sh[];
    int* A = sh;
    int* B = sh + CC_CELLS;
    int tid = threadIdx.x;
    int gx0 = blockIdx.x*64 - 32, gy0 = blockIdx.y*64 - 32;

    for (int s = tid; s < CC_CELLS; s += 1024){ A[s] = BIGL; B[s] = BIGL; }
    __syncthreads();

    #pragma unroll
    for (int k = 0; k < 4; k++){
        int v = tid + k*1024;
        int vy = v >> 5, vx = (v & 31)*4;
        int gy = gy0 + vy, gxb = gx0 + vx;
        int off = (1+vy)*CC_STRIDE + 4 + vx;
        if ((unsigned)gy < 2048u){
            if (gxb >= 0 && gxb + 3 < 2048){
                *(int4*)(A + off) = *(const int4*)(src + (gy<<11) + gxb);
            } else {
                #pragma unroll
                for (int e = 0; e < 4; e++){
                    int gx = gxb + e;
                    A[off+e] = ((unsigned)gx < 2048u) ? src[(gy<<11)+gx] : BIGL;
                }
            }
        }
    }
    __syncthreads();

    int vy0 = tid >> 5,          cx0 = (tid & 31)*4;
    int off0 = (1 + vy0)*CC_STRIDE + 4 + cx0;
    int vy1 = vy0 + 32;
    int off1 = off0 + 32*CC_STRIDE;
    int vy2 = vy0 + 64;
    int off2 = off0 + 64*CC_STRIDE;
    int vy3 = vy0 + 96;
    int off3 = off0 + 96*CC_STRIDE;

    int* cur = A; int* nxt = B;
    for (int s = 1; s <= 32; s++){
        int changed = 0;
        bool cok = (cx0+3 >= s) && (cx0 <= 127-s);
        if (cok){
            if (vy0 >= s && vy0 <= 127-s) changed |= cc_step(cur, nxt, off0);
            if (vy1 >= s && vy1 <= 127-s) changed |= cc_step(cur, nxt, off1);
            if (vy2 >= s && vy2 <= 127-s) changed |= cc_step(cur, nxt, off2);
            if (vy3 >= s && vy3 <= 127-s) changed |= cc_step(cur, nxt, off3);
        }
        if (!__syncthreads_or(changed)) break;
        int* t = cur; cur = nxt; nxt = t;
    }

    int row = tid >> 4, c16 = tid & 15;
    int soff = (33 + row)*CC_STRIDE + 36 + c16*4;
    int gy = blockIdx.y*64 + row, gx = blockIdx.x*64 + c16*4;
    *(int4*)(dst + (gy<<11) + gx) = *(const int4*)(cur + soff);
}

// ---------------- histogram (bbinit folded in) ----------------
__global__ void k_zero_counts(){
    int i = blockIdx.x*1024 + threadIdx.x;
    if (i < NLBL) g_counts[i] = 0;
    if (blockIdx.x == 0 && threadIdx.x < 16){
        g_bbox[threadIdx.x][0] = 0x7FFFFFFF; g_bbox[threadIdx.x][1] = -1;
        g_bbox[threadIdx.x][2] = 0x7FFFFFFF; g_bbox[threadIdx.x][3] = -1;
    }
}
__global__ void k_count(){
    int p4 = (blockIdx.x*256 + threadIdx.x)*4;
    int4 l = *(const int4*)(g_labA + p4);
    bool allbg = (l.x == BIGL) & (l.y == BIGL) & (l.z == BIGL) & (l.w == BIGL);
    if (__ballot_sync(0xffffffffu, !allbg) == 0u) return;   // whole warp background
    #pragma unroll
    for (int k = 0; k < 4; k++){
        int lab = (k==0) ? l.x : (k==1) ? l.y : (k==2) ? l.z : l.w;
        unsigned mk = __match_any_sync(0xffffffffu, lab);
        int leader = __ffs(mk) - 1;
        if ((threadIdx.x & 31) == leader && lab != BIGL)
            atomicAdd(&g_counts[lab], __popc(mk));
    }
}

// ---------------- exact top-16 (count desc, label asc): two-stage ----------------
__global__ void k_topA(){
    __shared__ unsigned long long s[256*16];
    int chunk = (NLBL + NBLK_TOP - 1)/NBLK_TOP;
    int lo = blockIdx.x*chunk;
    int hi = min(NLBL, lo + chunk);
    unsigned long long best[16];
    #pragma unroll
    for (int i = 0; i < 16; i++) best[i] = 0ull;
    unsigned long long bmin = 0ull; int bpos = 0;
    for (int i = lo + threadIdx.x; i < hi; i += 256){
        unsigned long long key = ((unsigned long long)(unsigned)g_counts[i] << 32)
                               | (unsigned)(~(unsigned)i);
        if (key > bmin){
            best[bpos] = key;
            bmin = best[0]; bpos = 0;
            #pragma unroll
            for (int j = 1; j < 16; j++) if (best[j] < bmin){ bmin = best[j]; bpos = j; }
        }
    }
    for (int j = 0; j < 16; j++) s[threadIdx.x*16 + j] = best[j];
    __syncthreads();
    if (threadIdx.x < 32){
        for (int r = 0; r < 16; r++){
            unsigned long long m = 0ull; int mp = -1;
            for (int i = threadIdx.x; i < 4096; i += 32){
                unsigned long long v = s[i];
                if (v > m){ m = v; mp = i; }
            }
            for (int off = 16; off; off >>= 1){
                unsigned long long om = __shfl_down_sync(0xffffffffu, m, off);
                int op = __shfl_down_sync(0xffffffffu, mp, off);
                if (om > m){ m = om; mp = op; }
            }
            m  = __shfl_sync(0xffffffffu, m, 0);
            mp = __shfl_sync(0xffffffffu, mp, 0);
            if (threadIdx.x == 0){
                g_cand[blockIdx.x*16 + r] = m;
                if (mp >= 0) s[mp] = 0ull;
            }
            __syncwarp();
        }
    }
}
__global__ void k_topB(){
    __shared__ unsigned long long s[2048];
    int tid = threadIdx.x;
    for (int i = tid; i < 2048; i += 256) s[i] = (i < NBLK_TOP*16) ? g_cand[i] : 0ull;
    __syncthreads();
    if (tid < 32){
        for (int r = 0; r < 16; r++){
            unsigned long long m = 0ull; int mp = -1;
            for (int i = tid; i < 2048; i += 32){
                unsigned long long v = s[i];
                if (v > m){ m = v; mp = i; }
            }
            for (int off = 16; off; off >>= 1){
                unsigned long long om = __shfl_down_sync(0xffffffffu, m, off);
                int op = __shfl_down_sync(0xffffffffu, mp, off);
                if (om > m){ m = om; mp = op; }
            }
            m  = __shfl_sync(0xffffffffu, m, 0);
            mp = __shfl_sync(0xffffffffu, mp, 0);
            if (tid == 0){
                g_cnts[r] = (int)(m >> 32);
                g_lids[r] = (int)(~(unsigned)(m & 0xffffffffull));
                if (mp >= 0) s[mp] = 0ull;
            }
            __syncwarp();
        }
    }
}

// ---------------- bounding boxes (int4 loads + background fast path) ----------------
__global__ void k_bbox(){
    __shared__ int slid[16];
    __shared__ int sbb[16][4];
    int tid = threadIdx.x;
    if (tid < 16){
        slid[tid] = g_lids[tid];
        sbb[tid][0] = 0x7FFFFFFF; sbb[tid][1] = -1; sbb[tid][2] = 0x7FFFFFFF; sbb[tid][3] = -1;
    }
    __syncthreads();
    int p4 = (blockIdx.x*256 + tid)*4;
    int4 l = *(const int4*)(g_labA + p4);
    if (!((l.x == BIGL) & (l.y == BIGL) & (l.z == BIGL) & (l.w == BIGL))){
        int y = p4 >> 11, xb = p4 & 2047;
        #pragma unroll
        for (int e = 0; e < 4; e++){
            int lab = (e==0) ? l.x : (e==1) ? l.y : (e==2) ? l.z : l.w;
            if (lab != BIGL){
                int x = xb + e;
                #pragma unroll
                for (int k = 0; k < 16; k++) if (lab == slid[k]){
                    if (y < sbb[k][0]) atomicMin(&sbb[k][0], y);
                    if (y > sbb[k][1]) atomicMax(&sbb[k][1], y);
                    if (x < sbb[k][2]) atomicMin(&sbb[k][2], x);
                    if (x > sbb[k][3]) atomicMax(&sbb[k][3], x);
                }
            }
        }
    }
    __syncthreads();
    if (tid < 16 && sbb[tid][0] != 0x7FFFFFFF){
        atomicMin(&g_bbox[tid][0], sbb[tid][0]);
        atomicMax(&g_bbox[tid][1], sbb[tid][1]);
        atomicMin(&g_bbox[tid][2], sbb[tid][2]);
        atomicMax(&g_bbox[tid][3], sbb[tid][3]);
    }
}

// ---------------- ROI bilinear resize (227x227), 8 blocks per ROI ----------------
__global__ void k_roi(const float* __restrict__ img){
    int k = blockIdx.x >> 3, part = blockIdx.x & 7;
    int y0 = g_bbox[k][0], y1 = g_bbox[k][1], x0 = g_bbox[k][2], x1 = g_bbox[k][3];
    if (y0 == 0x7FFFFFFF){ y0 = 0; y1 = 2047; x0 = 0; x1 = 2047; }
    float dy = (float)(y1 - y0), dx = (float)(x1 - x0);
    for (int idx = part*256 + threadIdx.x; idx < 227*227; idx += 2048){
        int i = idx/227, j = idx%227;
        float gy = (float)y0 + ((float)i/226.0f)*dy;
        float gx = (float)x0 + ((float)j/226.0f)*dx;
        int yf = min(max((int)floorf(gy), 0), 2046);
        int xf = min(max((int)floorf(gx), 0), 2046);
        float fy = gy - (float)yf, fx = gx - (float)xf;
        const float* r0 = img + (yf<<11) + xf;
        float v00 = r0[0], v01 = r0[1], v10 = r0[2048], v11 = r0[2049];
        g_roi[k*51529 + idx] = (1.f-fy)*((1.f-fx)*v00 + fx*v01) + fy*((1.f-fx)*v10 + fx*v11);
    }
}

// ---------------- classifier conv1: 7x7 s4 VALID, 1->16, relu ----------------
__global__ void k_c1(const float* __restrict__ cw1){
    __shared__ float sw[784];
    int tid = threadIdx.x;
    for (int i = tid; i < 784; i += 256) sw[i] = cw1[i];
    __syncthreads();
    int o = blockIdx.x*256 + tid;
    int k = o/50176, r = o%50176, oc = r/3136, s = r%3136, oy = s/56, ox = s%56;
    const float* roi = g_roi + k*51529;
    const float* wb = sw + oc*49;
    float a = 0.f;
    #pragma unroll
    for (int ky = 0; ky < 7; ky++){
        const float* rr = roi + (oy*4+ky)*227 + ox*4;
        #pragma unroll
        for (int kx = 0; kx < 7; kx++) a += rr[kx]*wb[ky*7+kx];
    }
    g_h1[o] = fmaxf(a, 0.f);
}

// ---------------- classifier conv2: 3x3 s2 VALID, 16->32, relu ----------------
__global__ void k_c2(const float* __restrict__ cw2){
    __shared__ float sw[4608];
    int tid = threadIdx.x;
    for (int i = tid; i < 4608; i += 256) sw[i] = cw2[i];
    __syncthreads();
    int o = blockIdx.x*256 + tid;
    int k = o/23328, r = o%23328, oc = r/729, s = r%729, oy = s/27, ox = s%27;
    const float* h = g_h1 + (size_t)k*16*3136;
    float a = 0.f;
    for (int ic = 0; ic < 16; ic++){
        const float* hb = h + ic*3136 + (oy*2)*56 + ox*2;
        const float* wb = sw + (oc*16+ic)*9;
        #pragma unroll
        for (int ky = 0; ky < 3; ky++)
            #pragma unroll
            for (int kx = 0; kx < 3; kx++)
                a += hb[ky*56+kx]*wb[ky*3+kx];
    }
    g_h2[o] = fmaxf(a, 0.f);
}

// ---------------- global mean + fc + argmax ----------------
__global__ void k_cls(const float* __restrict__ fc){
    __shared__ float ssum[32];
    int k = blockIdx.x;
    int tid = threadIdx.x, w = tid >> 5, lane = tid & 31;
    for (int oc = w*4; oc < w*4+4; oc++){
        float s = 0.f;
        const float* h = g_h2 + ((size_t)(k*32+oc))*729;
        for (int i = lane; i < 729; i += 32) s += h[i];
        for (int off = 16; off; off >>= 1) s += __shfl_down_sync(0xffffffffu, s, off);
        if (lane == 0) ssum[oc] = s;
    }
    __syncthreads();
    if (tid == 0){
        float best = -1e30f; int bc = 0;
        for (int c = 0; c < 4; c++){
            float lg = 0.f;
            for (int oc = 0; oc < 32; oc++) lg += (ssum[oc]*(1.0f/729.0f))*fc[oc*4+c];
            if (lg > best){ best = lg; bc = c; }
        }
        g_cls[k] = bc;
    }
}

// ---------------- final mask composition (vectorized) ----------------
__global__ void k_final(float* __restrict__ out){
    __shared__ int slid[16], scls[16];
    int tid = threadIdx.x;
    if (tid < 16){
        slid[tid] = (g_cnts[tid] >= MINSZ) ? g_lids[tid] : -1;
        scls[tid] = g_cls[tid];
    }
    __syncthreads();
    int p4 = (blockIdx.x*256 + tid)*4;
    int4 l = *(const int4*)(g_labA + p4);
    int c0 = -1, c1 = -1, c2 = -1, c3 = -1;
    #pragma unroll
    for (int k = 0; k < 16; k++){
        int lid = slid[k], cc = scls[k];
        if (l.x == lid) c0 = cc;
        if (l.y == lid) c1 = cc;
        if (l.z == lid) c2 = cc;
        if (l.w == lid) c3 = cc;
    }
    #pragma unroll
    for (int ch = 0; ch < 4; ch++){
        float4 o;
        o.x = (c0 == ch) ? 1.f : 0.f;
        o.y = (c1 == ch) ? 1.f : 0.f;
        o.z = (c2 == ch) ? 1.f : 0.f;
        o.w = (c3 == ch) ? 1.f : 0.f;
        *(float4*)(out + (size_t)ch*NPIX + p4) = o;
    }
}

// ---------------- launch ----------------
extern "C" void kernel_launch(void* const* d_in, const int* in_sizes, int n_in,
                              void* d_out, int out_size){
    const float *x = nullptr, *w1 = nullptr, *w2 = nullptr, *w3 = nullptr;
    const float *cw1 = nullptr, *cw2 = nullptr, *fc = nullptr;
    for (int i = 0; i < n_in; i++){
        switch (in_sizes[i]){
            case 4194304: x   = (const float*)d_in[i]; break;
            case 288:     w1  = (const float*)d_in[i]; break;
            case 9216:    w2  = (const float*)d_in[i]; break;
            case 32:      w3  = (const float*)d_in[i]; break;
            case 784:     cw1 = (const float*)d_in[i]; break;
            case 4608:    cw2 = (const float*)d_in[i]; break;
            case 128:     fc  = (const float*)d_in[i]; break;
            default: break;
        }
    }
    float* out = (float*)d_out;

    cudaFuncSetAttribute(k_conv_tc, cudaFuncAttributeMaxDynamicSharedMemorySize, CONV_SMEM);
    cudaFuncSetAttribute(k_cc, cudaFuncAttributeMaxDynamicSharedMemorySize, CC_SMEM);

    k_conv_tc<<<dim3(64,64), 256, CONV_SMEM>>>(x, w1, w2, w3);

    int* la = nullptr; int* lb = nullptr;
    cudaGetSymbolAddress((void**)&la, g_labA);
    cudaGetSymbolAddress((void**)&lb, g_labB);
    k_cc<<<dim3(32,32), 1024, CC_SMEM>>>(la, lb);   // 32 steps A -> B
    k_cc<<<dim3(32,32), 1024, CC_SMEM>>>(lb, la);   // 32 steps B -> A

    k_zero_counts<<<(NLBL+1023)/1024, 1024>>>();
    k_count<<<NPIX/1024, 256>>>();
    k_topA<<<NBLK_TOP, 256>>>();
    k_topB<<<1, 256>>>();

    k_bbox<<<NPIX/1024, 256>>>();

    k_roi<<<128, 256>>>(x);
    k_c1<<<802816/256, 256>>>(cw1);
    k_c2<<<373248/256, 256>>>(cw2);
    k_cls<<<16, 256>>>(fc);

    k_final<<<NPIX/1024, 256>>>(out);
}